// round 1
// baseline (speedup 1.0000x reference)
#include <cuda_runtime.h>
#include <cuda_bf16.h>

// Problem dims
#define NBATCH 2
#define NC 64
#define NT 16
#define NH 64
#define NW 64
#define PLANE 4096                    // NH*NW
static const size_t VOL = (size_t)NBATCH * NC * NT * PLANE;   // 8388608

// ---------------- scratch (__device__ globals; no runtime allocation) ------
__device__ float2 g_Af[(size_t)NC * NT * PLANE];      // 33.5 MB
__device__ float2 g_Bf[(size_t)NC * NT * PLANE];      // 33.5 MB
__device__ float2 g_PA[NC * NT * 9];
__device__ float2 g_PB[NC * NT * 9];
__device__ float2 g_QA[NC * NT * NH * 3];
__device__ float2 g_QB[NC * NT * NH * 3];
__device__ float  g_g [(size_t)NBATCH * NC * NT * PLANE];   // 33.5 MB
__device__ float  g_u [(size_t)NBATCH * NC * NT * PLANE];   // 33.5 MB
__device__ float  g_xT[(size_t)NBATCH * NC * NT * PLANE];   // 33.5 MB (reused as yT)
__device__ float2 g_X [(size_t)NBATCH * NC * NT * PLANE];   // 67 MB (X then h_f in place)

// ---------------- twiddle table: W64^k = exp(-2*pi*i*k/64), k=0..31 --------
__device__ const float2 gW64[32] = {
    { 1.00000000f, -0.00000000f}, { 0.99518473f, -0.09801714f},
    { 0.98078528f, -0.19509032f}, { 0.95694034f, -0.29028468f},
    { 0.92387953f, -0.38268343f}, { 0.88192126f, -0.47139674f},
    { 0.83146961f, -0.55557023f}, { 0.77301045f, -0.63439328f},
    { 0.70710678f, -0.70710678f}, { 0.63439328f, -0.77301045f},
    { 0.55557023f, -0.83146961f}, { 0.47139674f, -0.88192126f},
    { 0.38268343f, -0.92387953f}, { 0.29028468f, -0.95694034f},
    { 0.19509032f, -0.98078528f}, { 0.09801714f, -0.99518473f},
    { 0.00000000f, -1.00000000f}, {-0.09801714f, -0.99518473f},
    {-0.19509032f, -0.98078528f}, {-0.29028468f, -0.95694034f},
    {-0.38268343f, -0.92387953f}, {-0.47139674f, -0.88192126f},
    {-0.55557023f, -0.83146961f}, {-0.63439328f, -0.77301045f},
    {-0.70710678f, -0.70710678f}, {-0.77301045f, -0.63439328f},
    {-0.83146961f, -0.55557023f}, {-0.88192126f, -0.47139674f},
    {-0.92387953f, -0.38268343f}, {-0.95694034f, -0.29028468f},
    {-0.98078528f, -0.19509032f}, {-0.99518473f, -0.09801714f}
};

// ---------------- complex helpers ------------------------------------------
__device__ __forceinline__ float2 cadd(float2 a, float2 b){ return make_float2(a.x+b.x, a.y+b.y); }
__device__ __forceinline__ float2 csub(float2 a, float2 b){ return make_float2(a.x-b.x, a.y-b.y); }
__device__ __forceinline__ float2 cmul(float2 a, float2 b){
    return make_float2(a.x*b.x - a.y*b.y, a.x*b.y + a.y*b.x);
}

template<int SGN>
__device__ __forceinline__ float2 tw64(int i){
    float2 t = gW64[i];
    if (SGN < 0) t.y = -t.y;     // conj for inverse
    return t;
}

__device__ __forceinline__ float2 shflx(float2 v, int m){
    v.x = __shfl_xor_sync(0xffffffffu, v.x, m);
    v.y = __shfl_xor_sync(0xffffffffu, v.y, m);
    return v;
}

// ---------------- warp FFT64: lane holds x[l], x[l+32] ---------------------
// Output: lane l holds X[2*brev5(l)] (v0) and X[2*brev5(l)+1] (v1).
template<int SGN>
__device__ __forceinline__ void fft64w(float2 &v0, float2 &v1, int lane){
    // stage 0 (span 32): in-lane
    float2 a = v0, b = v1;
    v0 = cadd(a, b);
    v1 = cmul(csub(a, b), tw64<SGN>(lane));
    // 5 cross-lane DIF stages on two independent 32-pt FFTs
    #pragma unroll
    for (int span = 16; span >= 1; span >>= 1){
        float2 o0 = shflx(v0, span);
        float2 o1 = shflx(v1, span);
        if (lane & span){
            float2 t = tw64<SGN>((lane & (span-1)) * (32/span));
            v0 = cmul(csub(o0, v0), t);
            v1 = cmul(csub(o1, v1), t);
        } else {
            v0 = cadd(v0, o0);
            v1 = cadd(v1, o1);
        }
    }
}

// ---------------- register FFT16 (natural in, natural out) -----------------
template<int SGN>
__device__ __forceinline__ void fft16(float2 v[16]){
    #pragma unroll
    for (int half = 8; half >= 1; half >>= 1){
        #pragma unroll
        for (int base = 0; base < 16; base += 2*half){
            #pragma unroll
            for (int j = 0; j < half; j++){
                float2 a = v[base+j], b = v[base+j+half];
                v[base+j] = cadd(a, b);
                v[base+j+half] = cmul(csub(a, b), tw64<SGN>(j * (32/half)));
            }
        }
    }
    // bit-reverse (4-bit) reorder: swaps {1,8}{2,4}{3,12}{5,10}{7,14}{11,13}
    float2 t;
    t=v[1];  v[1]=v[8];   v[8]=t;
    t=v[2];  v[2]=v[4];   v[4]=t;
    t=v[3];  v[3]=v[12];  v[12]=t;
    t=v[5];  v[5]=v[10];  v[10]=t;
    t=v[7];  v[7]=v[14];  v[14]=t;
    t=v[11]; v[11]=v[13]; v[13]=t;
}

// ---------------- f32x2 packed FMA helpers ---------------------------------
__device__ __forceinline__ unsigned long long pk2(float a, float b){
    unsigned long long r;
    asm("mov.b64 %0, {%1,%2};" : "=l"(r) : "f"(a), "f"(b));
    return r;
}
__device__ __forceinline__ float2 upk2(unsigned long long v){
    float2 f;
    asm("mov.b64 {%0,%1}, %2;" : "=f"(f.x), "=f"(f.y) : "l"(v));
    return f;
}
__device__ __forceinline__ unsigned long long ffma2(unsigned long long a,
                                                    unsigned long long b,
                                                    unsigned long long c){
    unsigned long long d;
    asm("fma.rn.f32x2 %0, %1, %2, %3;" : "=l"(d) : "l"(a), "l"(b), "l"(c));
    return d;
}

__device__ __forceinline__ float sigmoidf_(float v){ return 1.0f / (1.0f + expf(-v)); }
__device__ __forceinline__ float softplusf_(float v){
    return fmaxf(v, 0.0f) + log1pf(expf(-fabsf(v)));
}

// ============ K0a: P[c,t,kh,kw] = sum_kt K[c,kt,kh,kw] * e_t ===============
__global__ void k0a(const float* __restrict__ Ak, const float* __restrict__ Bk){
    int i = blockIdx.x*blockDim.x + threadIdx.x;   // 64*16*9 = 9216
    if (i >= NC*NT*9) return;
    int kw = i % 3, kh = (i/3) % 3, t = (i/9) % NT, c = i/(9*NT);
    float2 aA = make_float2(0.f,0.f), aB = make_float2(0.f,0.f);
    #pragma unroll
    for (int kt = 0; kt < 3; kt++){
        float s, co;
        sincospif(-2.0f * (float)t * (float)(kt-1) / (float)NT, &s, &co);
        float ka = Ak[((c*3+kt)*3+kh)*3+kw];
        float kb = Bk[((c*3+kt)*3+kh)*3+kw];
        aA.x += ka*co; aA.y += ka*s;
        aB.x += kb*co; aB.y += kb*s;
    }
    g_PA[i] = aA; g_PB[i] = aB;
}

// ============ K0b: Q[c,t,h,kw] = sum_kh P[c,t,kh,kw] * e_h =================
__global__ void k0b(){
    int i = blockIdx.x*blockDim.x + threadIdx.x;   // 64*16*64*3 = 196608
    if (i >= NC*NT*NH*3) return;
    int kw = i % 3, h = (i/3) % NH, t = (i/192) % NT, c = i/(192*NT);
    int pb = (c*NT + t)*9 + kw;
    float2 aA = make_float2(0.f,0.f), aB = make_float2(0.f,0.f);
    #pragma unroll
    for (int kh = 0; kh < 3; kh++){
        float s, co;
        sincospif(-2.0f * (float)h * (float)(kh-1) / (float)NH, &s, &co);
        float2 e = make_float2(co, s);
        aA = cadd(aA, cmul(g_PA[pb + kh*3], e));
        aB = cadd(aB, cmul(g_PB[pb + kh*3], e));
    }
    g_QA[i] = aA; g_QB[i] = aB;
}

// ============ K0c: Af[c,t,h,w] = sum_kw Q[c,t,h,kw] * e_w ==================
__global__ void k0c(){
    int i = blockIdx.x*blockDim.x + threadIdx.x;   // 4194304
    int w = i & 63, h = (i>>6) & 63, t = (i>>12) & 15, c = i >> 16;
    int qb = ((c*NT + t)*NH + h)*3;
    float s, co;
    sincospif(2.0f * (float)w / (float)NW, &s, &co);
    float2 ep = make_float2(co,  s);   // kw=0  -> exp(+2*pi*i*w/64)
    float2 em = make_float2(co, -s);   // kw=2  -> exp(-2*pi*i*w/64)
    float2 aA = cadd(cadd(cmul(g_QA[qb+0], ep), g_QA[qb+1]), cmul(g_QA[qb+2], em));
    float2 aB = cadd(cadd(cmul(g_QB[qb+0], ep), g_QB[qb+1]), cmul(g_QB[qb+2], em));
    g_Af[i] = aA; g_Bf[i] = aB;
}

// ============ K1: gates + delta GEMV + transpose ===========================
// block per (b,t,h); reads x[b,t,h,:,:] (w,c) tile; writes g,u,xT (b,c,t,h,w)
__global__ __launch_bounds__(256) void k1(
    const float* __restrict__ x,  const float* __restrict__ dW,
    const float* __restrict__ db, const float* __restrict__ fb,
    const float* __restrict__ fs, const float* __restrict__ ib,
    const float* __restrict__ isc)
{
    __shared__ float xs[64*65];
    __shared__ float Ws[64*66];
    int blk = blockIdx.x;                 // (b,t,h)
    int b = blk >> 10, t = (blk >> 6) & 15, h = blk & 63;
    size_t xbase = (size_t)blk * PLANE;
    int tid = threadIdx.x;

    #pragma unroll
    for (int i = 0; i < 16; i++){
        int idx = tid + i*256;
        xs[(idx>>6)*65 + (idx&63)] = x[xbase + idx];      // xs[w][c]
        Ws[(idx>>6)*66 + (idx&63)] = dW[idx];             // Ws[c][d]
    }
    __syncthreads();

    int w   = tid & 63;
    int ddb = (tid >> 6) << 4;            // 16 output channels per thread

    unsigned long long acc[8];
    #pragma unroll
    for (int j = 0; j < 8; j++) acc[j] = pk2(db[ddb+2*j], db[ddb+2*j+1]);

    #pragma unroll 4
    for (int c = 0; c < 64; c++){
        float xv = xs[w*65 + c];
        unsigned long long xp = pk2(xv, xv);
        const unsigned long long* wrow =
            reinterpret_cast<const unsigned long long*>(&Ws[c*66 + ddb]);
        #pragma unroll
        for (int j = 0; j < 8; j++) acc[j] = ffma2(xp, wrow[j], acc[j]);
    }

    #pragma unroll
    for (int jj = 0; jj < 8; jj++){
        float2 dp = upk2(acc[jj]);
        #pragma unroll
        for (int k = 0; k < 2; k++){
            int ch = ddb + 2*jj + k;
            float dv = k ? dp.y : dp.x;
            float delta = softplusf_(dv);
            float xv = xs[w*65 + ch];
            float gv = sigmoidf_(fb[ch] + fs[ch]*xv);
            float uv = sigmoidf_(ib[ch] + isc[ch]*xv) * delta;
            size_t o = (((size_t)(b*NC + ch)*NT + t) * PLANE) + h*64 + w;
            g_g[o]  = gv;
            g_u[o]  = uv;
            g_xT[o] = xv;
        }
    }
}

// ============ K2: forward 2D FFT (W then H) per (b,c,t) plane ==============
__global__ __launch_bounds__(256) void k2(){
    __shared__ float sre[64*65];
    __shared__ float sim[64*65];
    size_t base = (size_t)blockIdx.x * PLANE;
    int tid = threadIdx.x, lane = tid & 31, wrp = tid >> 5;

    #pragma unroll
    for (int i = 0; i < 16; i++){
        int idx = tid + i*256; int h = idx>>6, w = idx&63;
        sre[h*65+w] = g_xT[base + idx];
        sim[h*65+w] = 0.0f;
    }
    __syncthreads();
    // rows: FFT along w
    #pragma unroll
    for (int r = 0; r < 8; r++){
        int h = wrp*8 + r;
        float2 v0 = make_float2(sre[h*65+lane],    sim[h*65+lane]);
        float2 v1 = make_float2(sre[h*65+lane+32], sim[h*65+lane+32]);
        fft64w<1>(v0, v1, lane);
        int i0 = 2*(int)(__brev((unsigned)lane) >> 27);
        sre[h*65+i0]   = v0.x; sim[h*65+i0]   = v0.y;
        sre[h*65+i0+1] = v1.x; sim[h*65+i0+1] = v1.y;
    }
    __syncthreads();
    // cols: FFT along h
    #pragma unroll
    for (int r = 0; r < 8; r++){
        int w = wrp*8 + r;
        float2 v0 = make_float2(sre[lane*65+w],      sim[lane*65+w]);
        float2 v1 = make_float2(sre[(lane+32)*65+w], sim[(lane+32)*65+w]);
        fft64w<1>(v0, v1, lane);
        int i0 = 2*(int)(__brev((unsigned)lane) >> 27);
        sre[i0*65+w]     = v0.x; sim[i0*65+w]     = v0.y;
        sre[(i0+1)*65+w] = v1.x; sim[(i0+1)*65+w] = v1.y;
    }
    __syncthreads();
    #pragma unroll
    for (int i = 0; i < 16; i++){
        int idx = tid + i*256; int h = idx>>6, w = idx&63;
        g_X[base + idx] = make_float2(sre[h*65+w], sim[h*65+w]);
    }
}

// ============ K3: FFT16 over T + gated scan + iFFT16 (in place) ============
__global__ __launch_bounds__(256) void k3(){
    int gid = blockIdx.x*blockDim.x + threadIdx.x;   // 524288 = B*C*H*W
    int hw = gid & 4095;
    int c  = (gid >> 12) & 63;
    int b  = gid >> 18;
    size_t xbase = ((size_t)(b*NC + c) * NT) * PLANE + hw;   // t stride = PLANE
    size_t fbase = ((size_t)c * NT) * PLANE + hw;

    float2 v[16];
    #pragma unroll
    for (int t = 0; t < 16; t++) v[t] = g_X[xbase + (size_t)t*PLANE];
    fft16<1>(v);

    float2 hst = make_float2(0.f, 0.f);
    #pragma unroll
    for (int t = 0; t < 16; t++){
        size_t o = (size_t)t * PLANE;
        float gv = g_g[xbase + o];
        float uv = g_u[xbase + o];
        float2 af = g_Af[fbase + o];
        float2 bf = g_Bf[fbase + o];
        float2 a  = make_float2(af.x*gv, af.y*gv);
        float2 bb = cmul(bf, v[t]);
        bb.x *= uv; bb.y *= uv;
        hst = cadd(cmul(a, hst), bb);
        v[t] = hst;
    }
    fft16<-1>(v);
    #pragma unroll
    for (int t = 0; t < 16; t++) g_X[xbase + (size_t)t*PLANE] = v[t];
}

// ============ K4: inverse 2D FFT per plane, real out (scaled) ==============
__global__ __launch_bounds__(256) void k4(){
    __shared__ float sre[64*65];
    __shared__ float sim[64*65];
    size_t base = (size_t)blockIdx.x * PLANE;
    int tid = threadIdx.x, lane = tid & 31, wrp = tid >> 5;

    #pragma unroll
    for (int i = 0; i < 16; i++){
        int idx = tid + i*256; int h = idx>>6, w = idx&63;
        float2 vv = g_X[base + idx];
        sre[h*65+w] = vv.x; sim[h*65+w] = vv.y;
    }
    __syncthreads();
    #pragma unroll
    for (int r = 0; r < 8; r++){
        int h = wrp*8 + r;
        float2 v0 = make_float2(sre[h*65+lane],    sim[h*65+lane]);
        float2 v1 = make_float2(sre[h*65+lane+32], sim[h*65+lane+32]);
        fft64w<-1>(v0, v1, lane);
        int i0 = 2*(int)(__brev((unsigned)lane) >> 27);
        sre[h*65+i0]   = v0.x; sim[h*65+i0]   = v0.y;
        sre[h*65+i0+1] = v1.x; sim[h*65+i0+1] = v1.y;
    }
    __syncthreads();
    #pragma unroll
    for (int r = 0; r < 8; r++){
        int w = wrp*8 + r;
        float2 v0 = make_float2(sre[lane*65+w],      sim[lane*65+w]);
        float2 v1 = make_float2(sre[(lane+32)*65+w], sim[(lane+32)*65+w]);
        fft64w<-1>(v0, v1, lane);
        int i0 = 2*(int)(__brev((unsigned)lane) >> 27);
        sre[i0*65+w]     = v0.x; sim[i0*65+w]     = v0.y;
        sre[(i0+1)*65+w] = v1.x; sim[(i0+1)*65+w] = v1.y;
    }
    __syncthreads();
    const float sc = 1.0f / 65536.0f;    // 1/(T*H*W)
    #pragma unroll
    for (int i = 0; i < 16; i++){
        int idx = tid + i*256; int h = idx>>6, w = idx&63;
        g_xT[base + idx] = sre[h*65+w] * sc;    // reuse xT as yT
    }
}

// ============ K5: transpose (b,c,t,h,w) -> (b,t,h,w,c) into d_out ==========
__global__ __launch_bounds__(256) void k5(float* __restrict__ out){
    __shared__ float s[64*65];
    int blk = blockIdx.x;                 // (b,t,h)
    int b = blk >> 10, t = (blk >> 6) & 15, h = blk & 63;
    int tid = threadIdx.x;
    #pragma unroll
    for (int i = 0; i < 16; i++){
        int idx = tid + i*256; int c = idx>>6, w = idx&63;
        s[c*65+w] = g_xT[(((size_t)(b*NC + c)*NT + t) * PLANE) + h*64 + w];
    }
    __syncthreads();
    size_t obase = (size_t)blk * PLANE;
    #pragma unroll
    for (int i = 0; i < 16; i++){
        int idx = tid + i*256; int w = idx>>6, c = idx&63;
        out[obase + idx] = s[c*65+w];     // idx = w*64 + c
    }
}

// ===========================================================================
extern "C" void kernel_launch(void* const* d_in, const int* in_sizes, int n_in,
                              void* d_out, int out_size)
{
    const float* x   = (const float*)d_in[0];
    const float* Ak  = (const float*)d_in[1];
    const float* Bk  = (const float*)d_in[2];
    const float* fb  = (const float*)d_in[3];
    const float* fs  = (const float*)d_in[4];
    const float* ib  = (const float*)d_in[5];
    const float* isc = (const float*)d_in[6];
    const float* dW  = (const float*)d_in[7];
    const float* db  = (const float*)d_in[8];
    float* out = (float*)d_out;

    k0a<<<36, 256>>>(Ak, Bk);            // 9216 threads
    k0b<<<768, 256>>>();                 // 196608 threads
    k0c<<<16384, 256>>>();               // 4194304 threads
    k1<<<2048, 256>>>(x, dW, db, fb, fs, ib, isc);
    k2<<<2048, 256>>>();                 // planes = B*C*T
    k3<<<2048, 256>>>();                 // B*C*H*W threads
    k4<<<2048, 256>>>();
    k5<<<2048, 256>>>(out);
}